// round 1
// baseline (speedup 1.0000x reference)
#include <cuda_runtime.h>
#include <math.h>

#define HW 200704
#define CC 192
#define NHEAD 6

// ---------------- scratch (static device globals; no allocation) ----------------
__device__ float g_mu[HW];
__device__ float g_rstd[HW];
__device__ float g_Wf[576 * CC];      // folded qkv_w@pre_w with ln_g, rows: q[0:192) k[192:384) v[384:576)
__device__ float g_bias[576];
__device__ float g_rowsum[576];
__device__ float g_G[CC * CC];        // Gram of normalized x (atomic split-K accumulator)
__device__ float g_s[CC];             // column sums of normalized x (atomic accumulator)
__device__ float g_T[384 * CC];       // T = W_{q,k} @ G
__device__ float g_u[384];            // u = W_{q,k} @ s
__device__ float g_gm[NHEAD * 32 * 32];
__device__ float g_v[CC * HW];        // v values (after epilogue affine)
__device__ float g_sm[CC * HW];       // softmax output

// ---------------- zero accumulators (must run every launch; graph replays) ------
__global__ void k_zero() {
    int i = blockIdx.x * 256 + threadIdx.x;
    if (i < CC * CC) g_G[i] = 0.f;
    if (i < CC)      g_s[i] = 0.f;
}

// ---------------- per-pixel LN stats --------------------------------------------
__global__ void k_stats(const float* __restrict__ x) {
    int p = blockIdx.x * 256 + threadIdx.x;
    float s = 0.f, ss = 0.f;
#pragma unroll 8
    for (int c = 0; c < CC; c++) {
        float v = x[c * HW + p];
        s += v; ss += v * v;
    }
    float mu  = s * (1.f / CC);
    float var = ss * (1.f / CC) - mu * mu;
    g_mu[p]   = mu;
    g_rstd[p] = rsqrtf(var + 1e-5f);
}

// ---------------- fold weights: Wf, rowsum, bias ---------------------------------
// qkv[o,p] = sum_j Wf[o,j] * xhat[j,p] + bias[o], xhat = (x-mu)*rstd
// Wf[o,j] = (sum_c qkv_w[o,c] pre_w[c,j]) * ln_g[j]
// bias[o] = sum_j (qkv_w@pre_w)[o,j]*ln_b[j] + sum_c qkv_w[o,c]*pre_b[c]
__global__ void k_fold(const float* __restrict__ qkv_w, const float* __restrict__ pre_w,
                       const float* __restrict__ ln_g, const float* __restrict__ ln_b,
                       const float* __restrict__ pre_b) {
    int o = blockIdx.x, j = threadIdx.x;
    float w2 = 0.f;
#pragma unroll 4
    for (int c = 0; c < CC; c++) w2 += qkv_w[o * CC + c] * pre_w[c * CC + j];
    float wf = w2 * ln_g[j];
    g_Wf[o * CC + j] = wf;
    __shared__ float s1[CC], s2[CC];
    s1[j] = wf;
    s2[j] = w2 * ln_b[j] + qkv_w[o * CC + j] * pre_b[j];
    __syncthreads();
    if (j < 64) { s1[j] += s1[j + 64] + s1[j + 128]; s2[j] += s2[j + 64] + s2[j + 128]; }
    __syncthreads();
    if (j < 32) {
        float a = s1[j] + s1[j + 32], b = s2[j] + s2[j + 32];
#pragma unroll
        for (int off = 16; off > 0; off >>= 1) {
            a += __shfl_down_sync(0xffffffffu, a, off);
            b += __shfl_down_sync(0xffffffffu, b, off);
        }
        if (j == 0) { g_rowsum[o] = a; g_bias[o] = b; }
    }
}

// ---------------- column sums of xhat (for bias corrections) --------------------
__global__ void k_colsum(const float* __restrict__ x) {
    int c = blockIdx.x;
    int p0 = blockIdx.y * 2048 + threadIdx.x;
    float acc = 0.f;
#pragma unroll
    for (int i = 0; i < 8; i++) {
        int p = p0 + i * 256;
        acc += (x[c * HW + p] - g_mu[p]) * g_rstd[p];
    }
    __shared__ float sh[256];
    int tid = threadIdx.x;
    sh[tid] = acc; __syncthreads();
    if (tid < 128) sh[tid] += sh[tid + 128]; __syncthreads();
    if (tid < 64)  sh[tid] += sh[tid + 64];  __syncthreads();
    if (tid < 32) {
        float a = sh[tid] + sh[tid + 32];
#pragma unroll
        for (int off = 16; off > 0; off >>= 1) a += __shfl_down_sync(0xffffffffu, a, off);
        if (tid == 0) atomicAdd(&g_s[c], a);
    }
}

// ---------------- Gram of xhat: G = Xhat @ Xhat^T  (split-K over pixels) --------
__global__ __launch_bounds__(256) void k_gram(const float* __restrict__ x) {
    __shared__ float As[32][64];
    __shared__ float Bs[32][64];
    int tid = threadIdx.x;
    int chunk = blockIdx.x;               // 98 chunks of 2048 pixels
    int ti = blockIdx.y % 3, tj = blockIdx.y / 3;
    int rowA = ti * 64, rowB = tj * 64;
    int tr = tid >> 4, tc = tid & 15;     // 16x16 threads, 4x4 outputs each
    float acc[4][4];
#pragma unroll
    for (int i = 0; i < 4; i++)
#pragma unroll
        for (int j = 0; j < 4; j++) acc[i][j] = 0.f;
    int lc = tid >> 2;                    // 0..63 channel within tile
    int lq = tid & 3;                     // 0..3 pixel quad
    int p0 = chunk * 2048;
    for (int kk = 0; kk < 2048; kk += 32) {
#pragma unroll
        for (int r = 0; r < 2; r++) {
            int q2 = lq + r * 4;
            int p4 = p0 + kk + q2 * 4;
            float4 mu4 = *(const float4*)(g_mu + p4);
            float4 rs4 = *(const float4*)(g_rstd + p4);
            float4 xa = *(const float4*)(x + (rowA + lc) * HW + p4);
            float4 xb = *(const float4*)(x + (rowB + lc) * HW + p4);
            As[q2 * 4 + 0][lc] = (xa.x - mu4.x) * rs4.x;
            As[q2 * 4 + 1][lc] = (xa.y - mu4.y) * rs4.y;
            As[q2 * 4 + 2][lc] = (xa.z - mu4.z) * rs4.z;
            As[q2 * 4 + 3][lc] = (xa.w - mu4.w) * rs4.w;
            Bs[q2 * 4 + 0][lc] = (xb.x - mu4.x) * rs4.x;
            Bs[q2 * 4 + 1][lc] = (xb.y - mu4.y) * rs4.y;
            Bs[q2 * 4 + 2][lc] = (xb.z - mu4.z) * rs4.z;
            Bs[q2 * 4 + 3][lc] = (xb.w - mu4.w) * rs4.w;
        }
        __syncthreads();
#pragma unroll
        for (int p = 0; p < 32; p++) {
            float4 a = *(const float4*)(&As[p][tr * 4]);
            float4 b = *(const float4*)(&Bs[p][tc * 4]);
            float av[4] = {a.x, a.y, a.z, a.w};
            float bv[4] = {b.x, b.y, b.z, b.w};
#pragma unroll
            for (int i = 0; i < 4; i++)
#pragma unroll
                for (int j = 0; j < 4; j++) acc[i][j] = fmaf(av[i], bv[j], acc[i][j]);
        }
        __syncthreads();
    }
#pragma unroll
    for (int i = 0; i < 4; i++)
#pragma unroll
        for (int j = 0; j < 4; j++)
            atomicAdd(&g_G[(rowA + tr * 4 + i) * CC + rowB + tc * 4 + j], acc[i][j]);
}

// ---------------- T = W_{q,k} @ G ; u = W_{q,k} @ s ------------------------------
__global__ void k_T() {
    int o = blockIdx.x, j = threadIdx.x;
    float acc = 0.f;
#pragma unroll 4
    for (int c = 0; c < CC; c++) acc += g_Wf[o * CC + c] * g_G[c * CC + j];
    g_T[o * CC + j] = acc;
    __shared__ float sh[CC];
    sh[j] = g_Wf[o * CC + j] * g_s[j];
    __syncthreads();
    if (j < 64) sh[j] += sh[j + 64] + sh[j + 128];
    __syncthreads();
    if (j < 32) {
        float a = sh[j] + sh[j + 32];
#pragma unroll
        for (int off = 16; off > 0; off >>= 1) a += __shfl_down_sync(0xffffffffu, a, off);
        if (j == 0) g_u[o] = a;
    }
}

// ---------------- attn -> mn -> gating -> gm (per head) --------------------------
__global__ __launch_bounds__(1024) void k_gm(const float* __restrict__ mn_w,
                                             const float* __restrict__ gating) {
    int h = blockIdx.x, tid = threadIdx.x;
    int d = tid >> 5, e = tid & 31;
    __shared__ float attn[32][33];
    __shared__ float nq[32], nk[32];
    if (tid < 64) {
        int o = (tid < 32) ? (h * 32 + tid) : (CC + h * 32 + (tid - 32));
        float acc = 0.f;
        for (int c2 = 0; c2 < CC; c2++) acc += g_T[o * CC + c2] * g_Wf[o * CC + c2];
        float b = g_bias[o];
        acc += 2.f * b * g_u[o] + (float)HW * b * b;
        float nval = fmaxf(sqrtf(fmaxf(acc, 0.f)), 1e-12f);
        if (tid < 32) nq[tid] = nval; else nk[tid - 32] = nval;
    }
    __syncthreads();
    int oq = h * 32 + d, ok = CC + h * 32 + e;
    float acc = 0.f;
    for (int c2 = 0; c2 < CC; c2++) acc += g_T[oq * CC + c2] * g_Wf[ok * CC + c2];
    acc += g_bias[ok] * g_u[oq] + g_bias[oq] * g_u[ok] + (float)HW * g_bias[oq] * g_bias[ok];
    attn[d][e] = acc / (nq[d] * nk[e]);
    __syncthreads();
    float g1 = gating[h], g2 = gating[NHEAD + h];
    float acc2 = 0.f;
#pragma unroll
    for (int e2 = 0; e2 < 32; e2++)
        acc2 += attn[d][e2] * (g1 * mn_w[e * 32 + e2] + g2 * mn_w[(32 + e) * 32 + e2]);
    g_gm[h * 1024 + d * 32 + e] = acc2;
}

// ---------------- mi = gm@cond ; softmax over d of mi*v --------------------------
__global__ __launch_bounds__(256) void k_softmax(const float* __restrict__ cond) {
    int h = blockIdx.y;
    int p = blockIdx.x * 256 + threadIdx.x;
    __shared__ float gm[1024];
    for (int i = threadIdx.x; i < 1024; i += 256) gm[i] = g_gm[h * 1024 + i];
    __syncthreads();
    float cv[32];
#pragma unroll
    for (int e = 0; e < 32; e++) cv[e] = cond[(h * 32 + e) * HW + p];
    float t[32];
    float mx = -1e30f;
#pragma unroll
    for (int d = 0; d < 32; d++) {
        float mi = 0.f;
#pragma unroll
        for (int e = 0; e < 32; e++) mi = fmaf(gm[d * 32 + e], cv[e], mi);
        float val = mi * g_v[(h * 32 + d) * HW + p];
        t[d] = val; mx = fmaxf(mx, val);
    }
    float sum = 0.f;
#pragma unroll
    for (int d = 0; d < 32; d++) { float ev = expf(t[d] - mx); t[d] = ev; sum += ev; }
    float inv = 1.f / sum;
#pragma unroll
    for (int d = 0; d < 32; d++) g_sm[(h * 32 + d) * HW + p] = t[d] * inv;
}

// ---------------- tiled GEMM: 64x128 tile, 256 threads, 4x8 per thread -----------
// mode 0: v = Wf[384:576] @ x, epilogue = LN affine; write g_v
// mode 1: out = proj_w @ g_sm + x; write Cout
__global__ __launch_bounds__(256) void k_gemm(const float* __restrict__ Ain,
                                              const float* __restrict__ Bin,
                                              float* __restrict__ Cout, int mode,
                                              const float* __restrict__ resid) {
    const float* A = (mode == 0) ? (g_Wf + 384 * CC) : Ain;
    const float* B = (mode == 0) ? Bin : g_sm;
    __shared__ float As[16][64];
    __shared__ float Bs[16][128];
    int tid = threadIdx.x;
    int bm = blockIdx.y, bn = blockIdx.x;
    int tr = tid >> 4, tc = tid & 15;
    float acc[4][8];
#pragma unroll
    for (int i = 0; i < 4; i++)
#pragma unroll
        for (int j = 0; j < 8; j++) acc[i][j] = 0.f;
    int am = tid >> 2, ak = (tid & 3) * 4;
    int bk = tid >> 4, bn8 = (tid & 15) * 8;
    const float* aptr = A + (bm * 64 + am) * CC + ak;
    const float* bptr = B + bk * HW + bn * 128 + bn8;
    for (int kk = 0; kk < CC; kk += 16) {
        float4 av = *(const float4*)(aptr + kk);
        float4 b0 = *(const float4*)(bptr + kk * HW);
        float4 b1 = *(const float4*)(bptr + kk * HW + 4);
        As[ak + 0][am] = av.x; As[ak + 1][am] = av.y;
        As[ak + 2][am] = av.z; As[ak + 3][am] = av.w;
        *(float4*)(&Bs[bk][bn8]) = b0;
        *(float4*)(&Bs[bk][bn8 + 4]) = b1;
        __syncthreads();
#pragma unroll
        for (int k = 0; k < 16; k++) {
            float4 a = *(const float4*)(&As[k][tr * 4]);
            float4 p0 = *(const float4*)(&Bs[k][tc * 8]);
            float4 p1 = *(const float4*)(&Bs[k][tc * 8 + 4]);
            float av4[4] = {a.x, a.y, a.z, a.w};
            float bv8[8] = {p0.x, p0.y, p0.z, p0.w, p1.x, p1.y, p1.z, p1.w};
#pragma unroll
            for (int i = 0; i < 4; i++)
#pragma unroll
                for (int j = 0; j < 8; j++) acc[i][j] = fmaf(av4[i], bv8[j], acc[i][j]);
        }
        __syncthreads();
    }
    int row0 = bm * 64 + tr * 4;
    int col0 = bn * 128 + tc * 8;
    if (mode == 0) {
        float muv[8], rsv[8];
#pragma unroll
        for (int j = 0; j < 8; j++) { muv[j] = g_mu[col0 + j]; rsv[j] = g_rstd[col0 + j]; }
#pragma unroll
        for (int i = 0; i < 4; i++) {
            int o = row0 + i;
            float rs = g_rowsum[384 + o], bi = g_bias[384 + o];
#pragma unroll
            for (int j = 0; j < 8; j++)
                g_v[o * HW + col0 + j] = rsv[j] * (acc[i][j] - muv[j] * rs) + bi;
        }
    } else {
#pragma unroll
        for (int i = 0; i < 4; i++) {
            int o = row0 + i;
#pragma unroll
            for (int j = 0; j < 8; j++)
                Cout[o * HW + col0 + j] = acc[i][j] + resid[o * HW + col0 + j];
        }
    }
}

// ---------------- launch ---------------------------------------------------------
extern "C" void kernel_launch(void* const* d_in, const int* in_sizes, int n_in,
                              void* d_out, int out_size) {
    const float* x      = (const float*)d_in[0];
    const float* cond   = (const float*)d_in[1];
    const float* ln_g   = (const float*)d_in[2];
    const float* ln_b   = (const float*)d_in[3];
    const float* pre_w  = (const float*)d_in[4];
    const float* pre_b  = (const float*)d_in[5];
    const float* qkv_w  = (const float*)d_in[6];
    const float* mn_w   = (const float*)d_in[7];
    const float* gating = (const float*)d_in[8];
    const float* proj_w = (const float*)d_in[9];
    float* out = (float*)d_out;

    k_zero<<<(CC * CC + 255) / 256, 256>>>();
    k_stats<<<HW / 256, 256>>>(x);
    k_fold<<<576, CC>>>(qkv_w, pre_w, ln_g, ln_b, pre_b);
    k_gemm<<<dim3(HW / 128, 3), 256>>>(nullptr, x, nullptr, 0, nullptr);   // v
    k_colsum<<<dim3(CC, HW / 2048), 256>>>(x);
    k_gram<<<dim3(HW / 2048, 9), 256>>>(x);
    k_T<<<384, CC>>>();
    k_gm<<<NHEAD, 1024>>>(mn_w, gating);
    k_softmax<<<dim3(HW / 256, NHEAD), 256>>>(cond);
    k_gemm<<<dim3(HW / 128, 3), 256>>>(proj_w, nullptr, out, 1, x);        // proj + residual
}

// round 2
// speedup vs baseline: 2.2714x; 2.2714x over previous
#include <cuda_runtime.h>
#include <cuda_bf16.h>
#include <math.h>

#define HW 200704
#define CC 192
#define NHEAD 6

// ---------------- scratch ----------------
__device__ float g_mu[HW];
__device__ float g_rstd[HW];
__device__ float g_Wf[576 * CC];
__device__ float g_bias[576];
__device__ float g_G[CC * CC];
__device__ float g_s[CC];
__device__ float g_T[384 * CC];
__device__ float g_u[384];
__device__ __align__(16) __nv_bfloat16 g_Wvb[CC * CC];   // v rows of folded weight, bf16
__device__ __align__(16) __nv_bfloat16 g_Wpb[CC * CC];   // proj_w bf16
__device__ __align__(16) __nv_bfloat16 g_gmbd[CC * CC];  // block-diag gm, bf16

// ---------------- mma helper ----------------
__device__ __forceinline__ void mma16816(float* c, const unsigned* a, const unsigned* b) {
    asm volatile(
        "mma.sync.aligned.m16n8k16.row.col.f32.bf16.bf16.f32 "
        "{%0,%1,%2,%3},{%4,%5,%6,%7},{%8,%9},{%0,%1,%2,%3};\n"
        : "+f"(c[0]), "+f"(c[1]), "+f"(c[2]), "+f"(c[3])
        : "r"(a[0]), "r"(a[1]), "r"(a[2]), "r"(a[3]), "r"(b[0]), "r"(b[1]));
}

// ---------------- zero accumulators ----------------
__global__ void k_zero() {
    int i = blockIdx.x * 256 + threadIdx.x;
    if (i < CC * CC) { g_G[i] = 0.f; g_gmbd[i] = __float2bfloat16(0.f); }
    if (i < CC) g_s[i] = 0.f;
}

// ---------------- per-pixel LN stats ----------------
__global__ void k_stats(const float* __restrict__ x) {
    int p = blockIdx.x * 256 + threadIdx.x;
    float s = 0.f, ss = 0.f;
#pragma unroll 8
    for (int c = 0; c < CC; c++) {
        float v = x[c * HW + p];
        s += v; ss += v * v;
    }
    float mu  = s * (1.f / CC);
    float var = ss * (1.f / CC) - mu * mu;
    g_mu[p]   = mu;
    g_rstd[p] = rsqrtf(var + 1e-5f);
}

// ---------------- fold weights ----------------
__global__ void k_fold(const float* __restrict__ qkv_w, const float* __restrict__ pre_w,
                       const float* __restrict__ ln_g, const float* __restrict__ ln_b,
                       const float* __restrict__ pre_b) {
    int o = blockIdx.x, j = threadIdx.x;
    float w2 = 0.f;
#pragma unroll 4
    for (int c = 0; c < CC; c++) w2 += qkv_w[o * CC + c] * pre_w[c * CC + j];
    float wf = w2 * ln_g[j];
    g_Wf[o * CC + j] = wf;
    if (o >= 384) g_Wvb[(o - 384) * CC + j] = __float2bfloat16(wf);
    __shared__ float s2[CC];
    s2[j] = w2 * ln_b[j] + qkv_w[o * CC + j] * pre_b[j];
    __syncthreads();
    if (j < 64) s2[j] += s2[j + 64] + s2[j + 128];
    __syncthreads();
    if (j < 32) {
        float b = s2[j] + s2[j + 32];
#pragma unroll
        for (int off = 16; off > 0; off >>= 1) b += __shfl_down_sync(0xffffffffu, b, off);
        if (j == 0) g_bias[o] = b;
    }
}

__global__ void k_cvt(const float* __restrict__ w) {
    int i = blockIdx.x * 256 + threadIdx.x;
    if (i < CC * CC) g_Wpb[i] = __float2bfloat16(w[i]);
}

// ---------------- Gram of xhat via bf16 mma (+ colsum fused) ----------------
// grid (HW/1024, 2): block computes G[0:192, y*96 : y*96+96] over 1024 pixels.
__global__ __launch_bounds__(256) void k_gram(const float* __restrict__ x) {
    __shared__ __align__(16) unsigned short xs[2][CC][40];
    int tid = threadIdx.x;
    int warp = tid >> 5, lane = tid & 31, gid = lane >> 2, tig = lane & 3;
    int m0 = (warp >> 1) * 48;
    int nbase = blockIdx.y * 96 + (warp & 1) * 48;
    int p0c = blockIdx.x * 1024;
    float acc[3][6][4];
#pragma unroll
    for (int f = 0; f < 3; f++)
#pragma unroll
        for (int g = 0; g < 6; g++)
#pragma unroll
            for (int r = 0; r < 4; r++) acc[f][g][r] = 0.f;
    float srow[12];
#pragma unroll
    for (int i = 0; i < 12; i++) srow[i] = 0.f;

    auto load_tile = [&](int it, int b) {
#pragma unroll
        for (int i = 0; i < 12; i++) {
            int q = tid + 256 * i;
            int c = q >> 4, pp = q & 15;
            int p = p0c + it * 32 + pp * 2;
            float2 xv = *(const float2*)(x + c * HW + p);
            float2 m2 = *(const float2*)(g_mu + p);
            float2 r2 = *(const float2*)(g_rstd + p);
            float h0 = (xv.x - m2.x) * r2.x;
            float h1 = (xv.y - m2.y) * r2.y;
            __nv_bfloat162 bb = __floats2bfloat162_rn(h0, h1);
            *(unsigned*)&xs[b][c][pp * 2] = *(unsigned*)&bb;
            if (blockIdx.y == 0) srow[i] += h0 + h1;
        }
    };

    load_tile(0, 0);
    __syncthreads();
    for (int it = 0; it < 32; it++) {
        int b = it & 1;
        if (it + 1 < 32) load_tile(it + 1, b ^ 1);
#pragma unroll
        for (int ks = 0; ks < 2; ks++) {
            int kl = ks * 16 + 2 * tig;
            unsigned a[3][4];
#pragma unroll
            for (int f = 0; f < 3; f++) {
                int r = m0 + f * 16 + gid;
                a[f][0] = *(const unsigned*)&xs[b][r][kl];
                a[f][1] = *(const unsigned*)&xs[b][r + 8][kl];
                a[f][2] = *(const unsigned*)&xs[b][r][kl + 8];
                a[f][3] = *(const unsigned*)&xs[b][r + 8][kl + 8];
            }
#pragma unroll
            for (int g = 0; g < 6; g++) {
                int n = nbase + g * 8 + gid;
                unsigned bb[2];
                bb[0] = *(const unsigned*)&xs[b][n][kl];
                bb[1] = *(const unsigned*)&xs[b][n][kl + 8];
#pragma unroll
                for (int f = 0; f < 3; f++) mma16816(acc[f][g], a[f], bb);
            }
        }
        __syncthreads();
    }
#pragma unroll
    for (int f = 0; f < 3; f++) {
        int m = m0 + f * 16 + gid;
#pragma unroll
        for (int g = 0; g < 6; g++) {
            int n = nbase + g * 8 + 2 * tig;
            atomicAdd(&g_G[m * CC + n],           acc[f][g][0]);
            atomicAdd(&g_G[m * CC + n + 1],       acc[f][g][1]);
            atomicAdd(&g_G[(m + 8) * CC + n],     acc[f][g][2]);
            atomicAdd(&g_G[(m + 8) * CC + n + 1], acc[f][g][3]);
        }
    }
    if (blockIdx.y == 0) {
#pragma unroll
        for (int i = 0; i < 12; i++) atomicAdd(&g_s[(tid + 256 * i) >> 4], srow[i]);
    }
}

// ---------------- T = W_{q,k} @ G ; u = W_{q,k} @ s ----------------
__global__ void k_T() {
    int o = blockIdx.x, j = threadIdx.x;
    float acc = 0.f;
#pragma unroll 4
    for (int c = 0; c < CC; c++) acc += g_Wf[o * CC + c] * g_G[c * CC + j];
    g_T[o * CC + j] = acc;
    __shared__ float sh[CC];
    sh[j] = g_Wf[o * CC + j] * g_s[j];
    __syncthreads();
    if (j < 64) sh[j] += sh[j + 64] + sh[j + 128];
    __syncthreads();
    if (j < 32) {
        float a = sh[j] + sh[j + 32];
#pragma unroll
        for (int off = 16; off > 0; off >>= 1) a += __shfl_down_sync(0xffffffffu, a, off);
        if (j == 0) g_u[o] = a;
    }
}

// ---------------- attn -> mn -> gating -> gm (block-diag bf16) ----------------
__global__ __launch_bounds__(1024) void k_gm(const float* __restrict__ mn_w,
                                             const float* __restrict__ gating) {
    int h = blockIdx.x, tid = threadIdx.x;
    int d = tid >> 5, e = tid & 31;
    __shared__ float attn[32][33];
    __shared__ float nq[32], nk[32];
    if (tid < 64) {
        int o = (tid < 32) ? (h * 32 + tid) : (CC + h * 32 + (tid - 32));
        float acc = 0.f;
        for (int c2 = 0; c2 < CC; c2++) acc += g_T[o * CC + c2] * g_Wf[o * CC + c2];
        float b = g_bias[o];
        acc += 2.f * b * g_u[o] + (float)HW * b * b;
        float nval = fmaxf(sqrtf(fmaxf(acc, 0.f)), 1e-12f);
        if (tid < 32) nq[tid] = nval; else nk[tid - 32] = nval;
    }
    __syncthreads();
    int oq = h * 32 + d, ok = CC + h * 32 + e;
    float acc = 0.f;
    for (int c2 = 0; c2 < CC; c2++) acc += g_T[oq * CC + c2] * g_Wf[ok * CC + c2];
    acc += g_bias[ok] * g_u[oq] + g_bias[oq] * g_u[ok] + (float)HW * g_bias[oq] * g_bias[ok];
    attn[d][e] = acc / (nq[d] * nk[e]);
    __syncthreads();
    float g1 = gating[h], g2 = gating[NHEAD + h];
    float acc2 = 0.f;
#pragma unroll
    for (int e2 = 0; e2 < 32; e2++)
        acc2 += attn[d][e2] * (g1 * mn_w[e * 32 + e2] + g2 * mn_w[(32 + e) * 32 + e2]);
    g_gmbd[(h * 32 + d) * CC + (h * 32 + e)] = __float2bfloat16(acc2);
}

// ---------------- fused kernel: 192x64 tiles, 3 bf16 mma GEMMs + softmax ----------
// smem layout (bytes): XH[64][200]bf16 @0, CD @25600, VS[64][196]f32 @51200,
//                      MI @101376, WS[192][40]bf16 @151552 ; total 166912
template <int MODE>
__device__ __forceinline__ void do_gemm(const __nv_bfloat16* __restrict__ Wg,
                                        const unsigned short* __restrict__ Bsm,
                                        unsigned short* __restrict__ WS,
                                        float* __restrict__ Cs,
                                        const float* __restrict__ xres,
                                        float* __restrict__ outg,
                                        int p0, int tid) {
    int warp = tid >> 5, lane = tid & 31, gid = lane >> 2, tig = lane & 3;
    int m0 = (warp >> 1) * 48, n0 = (warp & 1) * 32;
    float acc[3][4][4];
#pragma unroll
    for (int f = 0; f < 3; f++)
#pragma unroll
        for (int g = 0; g < 4; g++)
#pragma unroll
            for (int r = 0; r < 4; r++) acc[f][g][r] = 0.f;
#pragma unroll 1
    for (int kk = 0; kk < CC; kk += 32) {
        __syncthreads();
#pragma unroll
        for (int i = 0; i < 12; i++) {
            int q = tid + i * 256;
            int row = q >> 4, kc = q & 15;
            *(unsigned*)&WS[row * 40 + kc * 2] = *(const unsigned*)(Wg + row * CC + kk + kc * 2);
        }
        __syncthreads();
#pragma unroll
        for (int ks = 0; ks < 2; ks++) {
            int kl = ks * 16 + 2 * tig;
            unsigned a[3][4];
#pragma unroll
            for (int f = 0; f < 3; f++) {
                int r = m0 + f * 16 + gid;
                a[f][0] = *(const unsigned*)&WS[r * 40 + kl];
                a[f][1] = *(const unsigned*)&WS[(r + 8) * 40 + kl];
                a[f][2] = *(const unsigned*)&WS[r * 40 + kl + 8];
                a[f][3] = *(const unsigned*)&WS[(r + 8) * 40 + kl + 8];
            }
#pragma unroll
            for (int g = 0; g < 4; g++) {
                int n = n0 + g * 8 + gid;
                unsigned bb[2];
                bb[0] = *(const unsigned*)&Bsm[n * 200 + kk + kl];
                bb[1] = *(const unsigned*)&Bsm[n * 200 + kk + kl + 8];
#pragma unroll
                for (int f = 0; f < 3; f++) mma16816(acc[f][g], a[f], bb);
            }
        }
    }
#pragma unroll
    for (int f = 0; f < 3; f++) {
        int m = m0 + f * 16 + gid;
#pragma unroll
        for (int g = 0; g < 4; g++) {
            int n = n0 + g * 8 + 2 * tig;
            if (MODE == 2) {
                float2 r0 = *(const float2*)(xres + m * HW + p0 + n);
                float2 r1 = *(const float2*)(xres + (m + 8) * HW + p0 + n);
                float2 o0 = make_float2(acc[f][g][0] + r0.x, acc[f][g][1] + r0.y);
                float2 o1 = make_float2(acc[f][g][2] + r1.x, acc[f][g][3] + r1.y);
                *(float2*)(outg + m * HW + p0 + n) = o0;
                *(float2*)(outg + (m + 8) * HW + p0 + n) = o1;
            } else {
                float b0v = (MODE == 0) ? g_bias[384 + m] : 0.f;
                float b1v = (MODE == 0) ? g_bias[384 + m + 8] : 0.f;
                Cs[n * 196 + m]           = acc[f][g][0] + b0v;
                Cs[(n + 1) * 196 + m]     = acc[f][g][1] + b0v;
                Cs[n * 196 + m + 8]       = acc[f][g][2] + b1v;
                Cs[(n + 1) * 196 + m + 8] = acc[f][g][3] + b1v;
            }
        }
    }
}

__global__ __launch_bounds__(256) void k_fused(const float* __restrict__ x,
                                               const float* __restrict__ cond,
                                               float* __restrict__ out) {
    extern __shared__ __align__(16) char smr[];
    unsigned short* XH = (unsigned short*)(smr);
    unsigned short* CD = (unsigned short*)(smr + 25600);
    float* VS = (float*)(smr + 51200);
    float* MI = (float*)(smr + 101376);
    unsigned short* WS = (unsigned short*)(smr + 151552);
    int tid = threadIdx.x;
    int p0 = blockIdx.x * 64;
    // stage xhat (bf16) and cond (bf16), pixel-major layout [n][c]
#pragma unroll
    for (int q = tid; q < 1536; q += 256) {
        int c  = (q >> 4) * 2;
        int n4 = (q & 15) * 4;
        float4 mu4 = *(const float4*)(g_mu + p0 + n4);
        float4 rs4 = *(const float4*)(g_rstd + p0 + n4);
        float4 xa = *(const float4*)(x + c * HW + p0 + n4);
        float4 xb = *(const float4*)(x + (c + 1) * HW + p0 + n4);
        float4 ca = *(const float4*)(cond + c * HW + p0 + n4);
        float4 cb = *(const float4*)(cond + (c + 1) * HW + p0 + n4);
        float mus[4] = {mu4.x, mu4.y, mu4.z, mu4.w};
        float rss[4] = {rs4.x, rs4.y, rs4.z, rs4.w};
        float xas[4] = {xa.x, xa.y, xa.z, xa.w};
        float xbs[4] = {xb.x, xb.y, xb.z, xb.w};
        float cas[4] = {ca.x, ca.y, ca.z, ca.w};
        float cbs[4] = {cb.x, cb.y, cb.z, cb.w};
#pragma unroll
        for (int j = 0; j < 4; j++) {
            __nv_bfloat162 hx = __floats2bfloat162_rn((xas[j] - mus[j]) * rss[j],
                                                      (xbs[j] - mus[j]) * rss[j]);
            *(unsigned*)&XH[(n4 + j) * 200 + c] = *(unsigned*)&hx;
            __nv_bfloat162 hc = __floats2bfloat162_rn(cas[j], cbs[j]);
            *(unsigned*)&CD[(n4 + j) * 200 + c] = *(unsigned*)&hc;
        }
    }
    // GEMM1: v = Wv @ xhat + bias   -> VS
    do_gemm<0>(g_Wvb, XH, WS, VS, nullptr, nullptr, p0, tid);
    // GEMM2: mi = gm_bd @ cond      -> MI
    do_gemm<1>(g_gmbd, CD, WS, MI, nullptr, nullptr, p0, tid);
    __syncthreads();
    // softmax over head-dim (32) per pixel; write bf16 result into XH
    for (int task = tid; task < 384; task += 256) {
        int h = task >> 6, n = task & 63;
        int base = n * 196 + h * 32;
        float t[32];
        float mx = -1e30f;
#pragma unroll
        for (int d = 0; d < 32; d++) {
            float v = MI[base + d] * VS[base + d];
            t[d] = v;
            mx = fmaxf(mx, v);
        }
        float s = 0.f;
#pragma unroll
        for (int d = 0; d < 32; d++) { float e = __expf(t[d] - mx); t[d] = e; s += e; }
        float inv = 1.f / s;
#pragma unroll
        for (int d2 = 0; d2 < 16; d2++) {
            __nv_bfloat162 hp = __floats2bfloat162_rn(t[2 * d2] * inv, t[2 * d2 + 1] * inv);
            *(unsigned*)&XH[n * 200 + h * 32 + 2 * d2] = *(unsigned*)&hp;
        }
    }
    // GEMM3: out = proj @ sm + x
    do_gemm<2>(g_Wpb, XH, WS, nullptr, x, out, p0, tid);
}

// ---------------- launch ----------------
extern "C" void kernel_launch(void* const* d_in, const int* in_sizes, int n_in,
                              void* d_out, int out_size) {
    const float* x      = (const float*)d_in[0];
    const float* cond   = (const float*)d_in[1];
    const float* ln_g   = (const float*)d_in[2];
    const float* ln_b   = (const float*)d_in[3];
    const float* pre_w  = (const float*)d_in[4];
    const float* pre_b  = (const float*)d_in[5];
    const float* qkv_w  = (const float*)d_in[6];
    const float* mn_w   = (const float*)d_in[7];
    const float* gating = (const float*)d_in[8];
    const float* proj_w = (const float*)d_in[9];
    float* out = (float*)d_out;

    cudaFuncSetAttribute(k_fused, cudaFuncAttributeMaxDynamicSharedMemorySize, 166912);

    k_zero<<<144, 256>>>();
    k_stats<<<HW / 256, 256>>>(x);
    k_fold<<<576, CC>>>(qkv_w, pre_w, ln_g, ln_b, pre_b);
    k_cvt<<<144, 256>>>(proj_w);
    k_gram<<<dim3(HW / 1024, 2), 256>>>(x);
    k_T<<<384, CC>>>();
    k_gm<<<NHEAD, 1024>>>(mn_w, gating);
    k_fused<<<HW / 64, 256, 166912>>>(x, cond, out);
}

// round 4
// speedup vs baseline: 2.6606x; 1.1714x over previous
#include <cuda_runtime.h>
#include <cuda_bf16.h>
#include <math.h>

#define HW 200704
#define CC 192
#define NHEAD 6

// ---------------- scratch ----------------
__device__ float g_mu[HW];
__device__ float g_rstd[HW];
__device__ float g_Wf[576 * CC];
__device__ float g_bias[576];
__device__ float g_G[CC * CC];
__device__ float g_s[CC];
__device__ float g_T[384 * CC];
__device__ float g_u[384];
__device__ __align__(16) __nv_bfloat16 g_Wvb[CC * CC];   // v rows of folded weight, bf16
__device__ __align__(16) __nv_bfloat16 g_Wpb[CC * CC];   // proj_w bf16
__device__ __align__(16) __nv_bfloat16 g_gmc[CC * 32];   // per-head gm blocks, compact [192][32]

// ---------------- mma helper ----------------
__device__ __forceinline__ void mma16816(float* c, const unsigned* a, const unsigned* b) {
    asm volatile(
        "mma.sync.aligned.m16n8k16.row.col.f32.bf16.bf16.f32 "
        "{%0,%1,%2,%3},{%4,%5,%6,%7},{%8,%9},{%0,%1,%2,%3};\n"
        : "+f"(c[0]), "+f"(c[1]), "+f"(c[2]), "+f"(c[3])
        : "r"(a[0]), "r"(a[1]), "r"(a[2]), "r"(a[3]), "r"(b[0]), "r"(b[1]));
}

// ---------------- zero accumulators ----------------
__global__ void k_zero() {
    int i = blockIdx.x * 256 + threadIdx.x;
    if (i < CC * CC) g_G[i] = 0.f;
    if (i < CC) g_s[i] = 0.f;
}

// ---------------- per-pixel LN stats ----------------
__global__ void k_stats(const float* __restrict__ x) {
    int p = blockIdx.x * 256 + threadIdx.x;
    float s = 0.f, ss = 0.f;
#pragma unroll 8
    for (int c = 0; c < CC; c++) {
        float v = x[c * HW + p];
        s += v; ss += v * v;
    }
    float mu  = s * (1.f / CC);
    float var = ss * (1.f / CC) - mu * mu;
    g_mu[p]   = mu;
    g_rstd[p] = rsqrtf(var + 1e-5f);
}

// ---------------- fold weights ----------------
__global__ void k_fold(const float* __restrict__ qkv_w, const float* __restrict__ pre_w,
                       const float* __restrict__ ln_g, const float* __restrict__ ln_b,
                       const float* __restrict__ pre_b) {
    int o = blockIdx.x, j = threadIdx.x;
    float w2 = 0.f;
#pragma unroll 4
    for (int c = 0; c < CC; c++) w2 += qkv_w[o * CC + c] * pre_w[c * CC + j];
    float wf = w2 * ln_g[j];
    g_Wf[o * CC + j] = wf;
    if (o >= 384) g_Wvb[(o - 384) * CC + j] = __float2bfloat16(wf);
    __shared__ float s2[CC];
    s2[j] = w2 * ln_b[j] + qkv_w[o * CC + j] * pre_b[j];
    __syncthreads();
    if (j < 64) s2[j] += s2[j + 64] + s2[j + 128];
    __syncthreads();
    if (j < 32) {
        float b = s2[j] + s2[j + 32];
#pragma unroll
        for (int off = 16; off > 0; off >>= 1) b += __shfl_down_sync(0xffffffffu, b, off);
        if (j == 0) g_bias[o] = b;
    }
}

__global__ void k_cvt(const float* __restrict__ w) {
    int i = blockIdx.x * 256 + threadIdx.x;
    if (i < CC * CC) g_Wpb[i] = __float2bfloat16(w[i]);
}

// ---------------- Gram of xhat: persistent, full 192x192 per block ----------------
#define NT (HW / 32)
__global__ __launch_bounds__(256) void k_gram(const float* __restrict__ x) {
    __shared__ __align__(16) unsigned short xs[2][CC][40];
    int tid = threadIdx.x;
    int warp = tid >> 5, lane = tid & 31, gid = lane >> 2, tig = lane & 3;
    int m0 = (warp & 3) * 48;
    int n0 = (warp >> 2) * 96;
    float acc[3][12][4];
#pragma unroll
    for (int f = 0; f < 3; f++)
#pragma unroll
        for (int g = 0; g < 12; g++)
#pragma unroll
            for (int r = 0; r < 4; r++) acc[f][g][r] = 0.f;
    float srow[12];
#pragma unroll
    for (int i = 0; i < 12; i++) srow[i] = 0.f;

    auto load_tile = [&](int t, int b) {
        int p0 = t * 32;
#pragma unroll
        for (int i = 0; i < 12; i++) {
            int q = tid + 256 * i;
            int c = q >> 4, pp = q & 15;
            int p = p0 + pp * 2;
            float2 xv = *(const float2*)(x + c * HW + p);
            float2 m2 = *(const float2*)(g_mu + p);
            float2 r2 = *(const float2*)(g_rstd + p);
            float h0 = (xv.x - m2.x) * r2.x;
            float h1 = (xv.y - m2.y) * r2.y;
            __nv_bfloat162 bb = __floats2bfloat162_rn(h0, h1);
            *(unsigned*)&xs[b][c][pp * 2] = *(unsigned*)&bb;
            srow[i] += h0 + h1;
        }
    };

    int t = blockIdx.x;
    int iter = 0;
    if (t < NT) {
        load_tile(t, 0);
        __syncthreads();
        while (t < NT) {
            int b = iter & 1;
            int tn = t + gridDim.x;
            if (tn < NT) load_tile(tn, b ^ 1);
#pragma unroll
            for (int ks = 0; ks < 2; ks++) {
                int kl = ks * 16 + 2 * tig;
                unsigned a[3][4];
#pragma unroll
                for (int f = 0; f < 3; f++) {
                    int r = m0 + f * 16 + gid;
                    a[f][0] = *(const unsigned*)&xs[b][r][kl];
                    a[f][1] = *(const unsigned*)&xs[b][r + 8][kl];
                    a[f][2] = *(const unsigned*)&xs[b][r][kl + 8];
                    a[f][3] = *(const unsigned*)&xs[b][r + 8][kl + 8];
                }
#pragma unroll
                for (int g = 0; g < 12; g++) {
                    int n = n0 + g * 8 + gid;
                    unsigned bb[2];
                    bb[0] = *(const unsigned*)&xs[b][n][kl];
                    bb[1] = *(const unsigned*)&xs[b][n][kl + 8];
#pragma unroll
                    for (int f = 0; f < 3; f++) mma16816(acc[f][g], a[f], bb);
                }
            }
            __syncthreads();
            t = tn; iter++;
        }
    }
#pragma unroll
    for (int f = 0; f < 3; f++) {
        int m = m0 + f * 16 + gid;
#pragma unroll
        for (int g = 0; g < 12; g++) {
            int n = n0 + g * 8 + 2 * tig;
            atomicAdd(&g_G[m * CC + n],           acc[f][g][0]);
            atomicAdd(&g_G[m * CC + n + 1],       acc[f][g][1]);
            atomicAdd(&g_G[(m + 8) * CC + n],     acc[f][g][2]);
            atomicAdd(&g_G[(m + 8) * CC + n + 1], acc[f][g][3]);
        }
    }
#pragma unroll
    for (int i = 0; i < 12; i++) atomicAdd(&g_s[(tid + 256 * i) >> 4], srow[i]);
}

// ---------------- T = W_{q,k} @ G ; u = W_{q,k} @ s ----------------
__global__ void k_T() {
    int o = blockIdx.x, j = threadIdx.x;
    float acc = 0.f;
#pragma unroll 4
    for (int c = 0; c < CC; c++) acc += g_Wf[o * CC + c] * g_G[c * CC + j];
    g_T[o * CC + j] = acc;
    __shared__ float sh[CC];
    sh[j] = g_Wf[o * CC + j] * g_s[j];
    __syncthreads();
    if (j < 64) sh[j] += sh[j + 64] + sh[j + 128];
    __syncthreads();
    if (j < 32) {
        float a = sh[j] + sh[j + 32];
#pragma unroll
        for (int off = 16; off > 0; off >>= 1) a += __shfl_down_sync(0xffffffffu, a, off);
        if (j == 0) g_u[o] = a;
    }
}

// ---------------- attn -> mn -> gating -> gm (compact bf16) ----------------
__global__ __launch_bounds__(1024) void k_gm(const float* __restrict__ mn_w,
                                             const float* __restrict__ gating) {
    int h = blockIdx.x, tid = threadIdx.x;
    int d = tid >> 5, e = tid & 31;
    __shared__ float attn[32][33];
    __shared__ float nq[32], nk[32];
    if (tid < 64) {
        int o = (tid < 32) ? (h * 32 + tid) : (CC + h * 32 + (tid - 32));
        float acc = 0.f;
        for (int c2 = 0; c2 < CC; c2++) acc += g_T[o * CC + c2] * g_Wf[o * CC + c2];
        float b = g_bias[o];
        acc += 2.f * b * g_u[o] + (float)HW * b * b;
        float nval = fmaxf(sqrtf(fmaxf(acc, 0.f)), 1e-12f);
        if (tid < 32) nq[tid] = nval; else nk[tid - 32] = nval;
    }
    __syncthreads();
    int oq = h * 32 + d, ok = CC + h * 32 + e;
    float acc = 0.f;
    for (int c2 = 0; c2 < CC; c2++) acc += g_T[oq * CC + c2] * g_Wf[ok * CC + c2];
    acc += g_bias[ok] * g_u[oq] + g_bias[oq] * g_u[ok] + (float)HW * g_bias[oq] * g_bias[ok];
    attn[d][e] = acc / (nq[d] * nk[e]);
    __syncthreads();
    float g1 = gating[h], g2 = gating[NHEAD + h];
    float acc2 = 0.f;
#pragma unroll
    for (int e2 = 0; e2 < 32; e2++)
        acc2 += attn[d][e2] * (g1 * mn_w[e * 32 + e2] + g2 * mn_w[(32 + e) * 32 + e2]);
    g_gmc[(h * 32 + d) * 32 + e] = __float2bfloat16(acc2);
}

// ---------------- fused kernel: 192x64 tiles, 3 bf16 mma GEMMs + softmax ----------
// smem: XH[64][200]bf16 @0, CD[64][200]bf16 @25600, TS[64][196]f32 @51200 = 101376 B
__global__ __launch_bounds__(256, 2) void k_fused(const float* __restrict__ x,
                                                  const float* __restrict__ cond,
                                                  float* __restrict__ out) {
    extern __shared__ __align__(16) char smr[];
    unsigned short* XH = (unsigned short*)(smr);
    unsigned short* CD = (unsigned short*)(smr + 25600);
    float* TS = (float*)(smr + 51200);
    int tid = threadIdx.x;
    int p0 = blockIdx.x * 64;
    int warp = tid >> 5, lane = tid & 31, gid = lane >> 2, tig = lane & 3;
    int m0 = (warp >> 1) * 48, n0 = (warp & 1) * 32;

    // ---- stage xhat (bf16) and cond (bf16), pixel-major [n][c] ----
#pragma unroll
    for (int q = tid; q < 1536; q += 256) {
        int c  = (q >> 4) * 2;
        int n4 = (q & 15) * 4;
        float4 mu4 = *(const float4*)(g_mu + p0 + n4);
        float4 rs4 = *(const float4*)(g_rstd + p0 + n4);
        float4 xa = *(const float4*)(x + c * HW + p0 + n4);
        float4 xb = *(const float4*)(x + (c + 1) * HW + p0 + n4);
        float4 ca = *(const float4*)(cond + c * HW + p0 + n4);
        float4 cb = *(const float4*)(cond + (c + 1) * HW + p0 + n4);
        float mus[4] = {mu4.x, mu4.y, mu4.z, mu4.w};
        float rss[4] = {rs4.x, rs4.y, rs4.z, rs4.w};
        float xas[4] = {xa.x, xa.y, xa.z, xa.w};
        float xbs[4] = {xb.x, xb.y, xb.z, xb.w};
        float cas[4] = {ca.x, ca.y, ca.z, ca.w};
        float cbs[4] = {cb.x, cb.y, cb.z, cb.w};
#pragma unroll
        for (int j = 0; j < 4; j++) {
            __nv_bfloat162 hx = __floats2bfloat162_rn((xas[j] - mus[j]) * rss[j],
                                                      (xbs[j] - mus[j]) * rss[j]);
            *(unsigned*)&XH[(n4 + j) * 200 + c] = *(unsigned*)&hx;
            __nv_bfloat162 hc = __floats2bfloat162_rn(cas[j], cbs[j]);
            *(unsigned*)&CD[(n4 + j) * 200 + c] = *(unsigned*)&hc;
        }
    }
    __syncthreads();

    // ---- GEMM1: v = Wv @ xhat (acc held in regs) ----
    float accv[3][4][4];
#pragma unroll
    for (int f = 0; f < 3; f++)
#pragma unroll
        for (int g = 0; g < 4; g++)
#pragma unroll
            for (int r = 0; r < 4; r++) accv[f][g][r] = 0.f;
#pragma unroll
    for (int kk = 0; kk < CC; kk += 32) {
#pragma unroll
        for (int ks = 0; ks < 2; ks++) {
            int kl = ks * 16 + 2 * tig;
            unsigned a[3][4];
#pragma unroll
            for (int f = 0; f < 3; f++) {
                int r = m0 + f * 16 + gid;
                a[f][0] = *(const unsigned*)&g_Wvb[r * CC + kk + kl];
                a[f][1] = *(const unsigned*)&g_Wvb[(r + 8) * CC + kk + kl];
                a[f][2] = *(const unsigned*)&g_Wvb[r * CC + kk + kl + 8];
                a[f][3] = *(const unsigned*)&g_Wvb[(r + 8) * CC + kk + kl + 8];
            }
#pragma unroll
            for (int g = 0; g < 4; g++) {
                int n = n0 + g * 8 + gid;
                unsigned bb[2];
                bb[0] = *(const unsigned*)&XH[n * 200 + kk + kl];
                bb[1] = *(const unsigned*)&XH[n * 200 + kk + kl + 8];
#pragma unroll
                for (int f = 0; f < 3; f++) mma16816(accv[f][g], a[f], bb);
            }
        }
    }

    // ---- GEMM2: mi = gm @ cond (block-diag: 1 k-chunk per m-tile) ----
    float accm[3][4][4];
#pragma unroll
    for (int f = 0; f < 3; f++)
#pragma unroll
        for (int g = 0; g < 4; g++)
#pragma unroll
            for (int r = 0; r < 4; r++) accm[f][g][r] = 0.f;
#pragma unroll
    for (int f = 0; f < 3; f++) {
        int row16 = m0 + f * 16;
        int kkf = (row16 >> 5) << 5;        // head-aligned k chunk
#pragma unroll
        for (int ks = 0; ks < 2; ks++) {
            int kl = ks * 16 + 2 * tig;
            unsigned a[4];
            int r = row16 + gid;
            a[0] = *(const unsigned*)&g_gmc[r * 32 + kl];
            a[1] = *(const unsigned*)&g_gmc[(r + 8) * 32 + kl];
            a[2] = *(const unsigned*)&g_gmc[r * 32 + kl + 8];
            a[3] = *(const unsigned*)&g_gmc[(r + 8) * 32 + kl + 8];
#pragma unroll
            for (int g = 0; g < 4; g++) {
                int n = n0 + g * 8 + gid;
                unsigned bb[2];
                bb[0] = *(const unsigned*)&CD[n * 200 + kkf + kl];
                bb[1] = *(const unsigned*)&CD[n * 200 + kkf + kl + 8];
                mma16816(accm[f][g], a, bb);
            }
        }
    }

    // ---- t = mi * (v + bias) -> TS ----
#pragma unroll
    for (int f = 0; f < 3; f++) {
        int m = m0 + f * 16 + gid;
        float bv0 = g_bias[384 + m];
        float bv1 = g_bias[384 + m + 8];
#pragma unroll
        for (int g = 0; g < 4; g++) {
            int n = n0 + g * 8 + 2 * tig;
            TS[n * 196 + m]           = accm[f][g][0] * (accv[f][g][0] + bv0);
            TS[(n + 1) * 196 + m]     = accm[f][g][1] * (accv[f][g][1] + bv0);
            TS[n * 196 + m + 8]       = accm[f][g][2] * (accv[f][g][2] + bv1);
            TS[(n + 1) * 196 + m + 8] = accm[f][g][3] * (accv[f][g][3] + bv1);
        }
    }
    __syncthreads();

    // ---- softmax over head-dim per pixel; probs (bf16) -> XH ----
    for (int task = tid; task < 384; task += 256) {
        int h = task >> 6, n = task & 63;
        int base = n * 196 + h * 32;
        float t[32];
        float mx = -1e30f;
#pragma unroll
        for (int d = 0; d < 32; d++) {
            float v = TS[base + d];
            t[d] = v;
            mx = fmaxf(mx, v);
        }
        float s = 0.f;
#pragma unroll
        for (int d = 0; d < 32; d++) { float e = __expf(t[d] - mx); t[d] = e; s += e; }
        float inv = 1.f / s;
#pragma unroll
        for (int d2 = 0; d2 < 16; d2++) {
            __nv_bfloat162 hp = __floats2bfloat162_rn(t[2 * d2] * inv, t[2 * d2 + 1] * inv);
            *(unsigned*)&XH[n * 200 + h * 32 + 2 * d2] = *(unsigned*)&hp;
        }
    }
    __syncthreads();

    // ---- GEMM3: out = proj @ probs + x ----
    float acc[3][4][4];
#pragma unroll
    for (int f = 0; f < 3; f++)
#pragma unroll
        for (int g = 0; g < 4; g++)
#pragma unroll
            for (int r = 0; r < 4; r++) acc[f][g][r] = 0.f;
#pragma unroll
    for (int kk = 0; kk < CC; kk += 32) {
#pragma unroll
        for (int ks = 0; ks < 2; ks++) {
            int kl = ks * 16 + 2 * tig;
            unsigned a[3][4];
#pragma unroll
            for (int f = 0; f < 3; f++) {
                int r = m0 + f * 16 + gid;
                a[f][0] = *(const unsigned*)&g_Wpb[r * CC + kk + kl];
                a[f][1] = *(const unsigned*)&g_Wpb[(r + 8) * CC + kk + kl];
                a[f][2] = *(const unsigned*)&g_Wpb[r * CC + kk + kl + 8];
                a[f][3] = *(const unsigned*)&g_Wpb[(r + 8) * CC + kk + kl + 8];
            }
#pragma unroll
            for (int g = 0; g < 4; g++) {
                int n = n0 + g * 8 + gid;
                unsigned bb[2];
                bb[0] = *(const unsigned*)&XH[n * 200 + kk + kl];
                bb[1] = *(const unsigned*)&XH[n * 200 + kk + kl + 8];
#pragma unroll
                for (int f = 0; f < 3; f++) mma16816(acc[f][g], a[f], bb);
            }
        }
    }
#pragma unroll
    for (int f = 0; f < 3; f++) {
        int m = m0 + f * 16 + gid;
#pragma unroll
        for (int g = 0; g < 4; g++) {
            int n = n0 + g * 8 + 2 * tig;
            float2 r0 = *(const float2*)(x + m * HW + p0 + n);
            float2 r1 = *(const float2*)(x + (m + 8) * HW + p0 + n);
            float2 o0 = make_float2(acc[f][g][0] + r0.x, acc[f][g][1] + r0.y);
            float2 o1 = make_float2(acc[f][g][2] + r1.x, acc[f][g][3] + r1.y);
            *(float2*)(out + m * HW + p0 + n) = o0;
            *(float2*)(out + (m + 8) * HW + p0 + n) = o1;
        }
    }
}

// ---------------- launch ----------------
extern "C" void kernel_launch(void* const* d_in, const int* in_sizes, int n_in,
                              void* d_out, int out_size) {
    const float* x      = (const float*)d_in[0];
    const float* cond   = (const float*)d_in[1];
    const float* ln_g   = (const float*)d_in[2];
    const float* ln_b   = (const float*)d_in[3];
    const float* pre_w  = (const float*)d_in[4];
    const float* pre_b  = (const float*)d_in[5];
    const float* qkv_w  = (const float*)d_in[6];
    const float* mn_w   = (const float*)d_in[7];
    const float* gating = (const float*)d_in[8];
    const float* proj_w = (const float*)d_in[9];
    float* out = (float*)d_out;

    cudaFuncSetAttribute(k_fused, cudaFuncAttributeMaxDynamicSharedMemorySize, 101376);

    k_zero<<<144, 256>>>();
    k_stats<<<HW / 256, 256>>>(x);
    k_fold<<<576, CC>>>(qkv_w, pre_w, ln_g, ln_b, pre_b);
    k_cvt<<<144, 256>>>(proj_w);
    k_gram<<<152, 256>>>(x);
    k_T<<<384, CC>>>();
    k_gm<<<NHEAD, 1024>>>(mn_w, gating);
    k_fused<<<HW / 64, 256, 101376>>>(x, cond, out);
}